// round 14
// baseline (speedup 1.0000x reference)
#include <cuda_runtime.h>
#include <cuda_bf16.h>
#include <cstdint>
#include <cstddef>

typedef unsigned long long u64;

#define BATCH 512
#define SEQT  1024

// ---------------- scratch (static device globals) -------------------------------
__device__ float g_g1[(size_t)BATCH * SEQT * 512];   // layer1 gate preacts (1.07 GB)
__device__ float g_g2[(size_t)BATCH * SEQT * 256];   // layer2-fwd gate preacts (536 MB)
__device__ float g_h1[(size_t)BATCH * SEQT * 128];   // layer1 h [fwd|bwd] fp32 (268 MB)
__device__ float g_h2[BATCH * 64];                   // layer2-fwd final h
__device__ __nv_bfloat16 g_wh[768 * 128];            // w_ih split-bf16 hi: l0d0,l0d1,l1d0
__device__ __nv_bfloat16 g_wl[768 * 128];            // w_ih split-bf16 lo

// ---------------- packed fp32x2 helpers -----------------------------------------
static __device__ __forceinline__ u64 pk2(float a, float b) {
    u64 r;
    asm("mov.b64 %0, {%1, %2};" : "=l"(r) : "r"(__float_as_uint(a)), "r"(__float_as_uint(b)));
    return r;
}
static __device__ __forceinline__ float2 upk2(u64 v) {
    unsigned int lo, hi;
    asm("mov.b64 {%0, %1}, %2;" : "=r"(lo), "=r"(hi) : "l"(v));
    return make_float2(__uint_as_float(lo), __uint_as_float(hi));
}
static __device__ __forceinline__ u64 fma2(u64 a, u64 b, u64 c) {
    u64 d;
    asm("fma.rn.f32x2 %0, %1, %2, %3;" : "=l"(d) : "l"(a), "l"(b), "l"(c));
    return d;
}
static __device__ __forceinline__ float sigf(float x) {
    return __fdividef(1.f, 1.f + __expf(-x));
}
static __device__ __forceinline__ float tnhf(float x) {
    return __fdividef(2.f, 1.f + __expf(-2.f * x)) - 1.f;
}

// ---------------- mma.sync / ldmatrix helpers ------------------------------------
static __device__ __forceinline__ uint32_t smem_u32(const void* p) {
    uint32_t a;
    asm("{ .reg .u64 t; cvta.to.shared.u64 t, %1; cvt.u32.u64 %0, t; }" : "=r"(a) : "l"(p));
    return a;
}
#define LDSM4(d0, d1, d2, d3, a)                                                     \
    asm volatile("ldmatrix.sync.aligned.m8n8.x4.shared.b16 {%0,%1,%2,%3}, [%4];"     \
                 : "=r"(d0), "=r"(d1), "=r"(d2), "=r"(d3) : "r"(a))

static __device__ __forceinline__ void mma16816(float* d, const uint32_t* a,
                                                const uint32_t* b) {
    asm volatile(
        "mma.sync.aligned.m16n8k16.row.col.f32.bf16.bf16.f32 "
        "{%0,%1,%2,%3}, {%4,%5,%6,%7}, {%8,%9}, {%0,%1,%2,%3};"
        : "+f"(d[0]), "+f"(d[1]), "+f"(d[2]), "+f"(d[3])
        : "r"(a[0]), "r"(a[1]), "r"(a[2]), "r"(a[3]), "r"(b[0]), "r"(b[1]));
}

// split one fp32 into bf16 hi + bf16 lo (residual)
static __device__ __forceinline__ void split8(const float* v, uint4& hi, uint4& lo) {
    unsigned hw[4], lw[4];
#pragma unroll
    for (int p = 0; p < 4; p++) {
        __nv_bfloat16 h0 = __float2bfloat16(v[2 * p]);
        __nv_bfloat16 h1 = __float2bfloat16(v[2 * p + 1]);
        float r0 = v[2 * p]     - __bfloat162float(h0);
        float r1 = v[2 * p + 1] - __bfloat162float(h1);
        __nv_bfloat16 l0 = __float2bfloat16(r0);
        __nv_bfloat16 l1 = __float2bfloat16(r1);
        hw[p] = (unsigned)(*(unsigned short*)&h0) | ((unsigned)(*(unsigned short*)&h1) << 16);
        lw[p] = (unsigned)(*(unsigned short*)&l0) | ((unsigned)(*(unsigned short*)&l1) << 16);
    }
    hi = make_uint4(hw[0], hw[1], hw[2], hw[3]);
    lo = make_uint4(lw[0], lw[1], lw[2], lw[3]);
}

// ---------------- weight split conversion (tiny) --------------------------------
__global__ void conv_w_k(const float* __restrict__ w) {
    int i = blockIdx.x * blockDim.x + threadIdx.x;
    if (i < 768 * 128) {
        float v = w[i];
        __nv_bfloat16 h = __float2bfloat16(v);
        g_wh[i] = h;
        g_wl[i] = __float2bfloat16(v - __bfloat162float(h));
    }
}

// ---------------- HMMA split-bf16 GEMM: C = A[M,128] @ W[N,128]^T + b -----------
__global__ __launch_bounds__(256, 1)
void gemm_mma(const float* __restrict__ x, const float* __restrict__ bih,
              const float* __restrict__ bhh, int which)
{
    const float* Asrc = which ? g_h1 : x;
    float*       C    = which ? g_g2 : g_g1;
    const int N    = which ? 256 : 512;
    const int NBLK = which ? 2 : 4;
    const int boff = which ? 512 : 0;
    const int brow = which ? 512 : 0;      // row offset into g_wh/g_wl

    extern __shared__ __align__(1024) char smem[];
    char* sAh = smem;                      // 32KB each, rows of 256B, chunk16 swizzle
    char* sAl = smem + 32768;
    char* sBh = smem + 65536;
    char* sBl = smem + 98304;
    const uint32_t aAh = smem_u32(sAh), aAl = smem_u32(sAl);
    const uint32_t aBh = smem_u32(sBh), aBl = smem_u32(sBl);

    const int tid  = threadIdx.x;
    const int lane = tid & 31;
    const int wid  = tid >> 5;
    const size_t mBase = (size_t)blockIdx.x * 128;

    // ---- stage A (fp32 -> split bf16), swizzled: off(r,c)=r*256+((c^(r&7))<<4)
    {
        const int ck = tid & 15;
        const int r0 = (tid >> 4) * 8;
#pragma unroll
        for (int i = 0; i < 8; i++) {
            int r = r0 + i;
            float vbuf[8];
            const float4* src = (const float4*)(Asrc + (mBase + r) * 128 + ck * 8);
            float4 v0 = src[0], v1 = src[1];
            vbuf[0] = v0.x; vbuf[1] = v0.y; vbuf[2] = v0.z; vbuf[3] = v0.w;
            vbuf[4] = v1.x; vbuf[5] = v1.y; vbuf[6] = v1.z; vbuf[7] = v1.w;
            uint4 hi, lo;
            split8(vbuf, hi, lo);
            int off = r * 256 + ((ck ^ (r & 7)) << 4);
            *(uint4*)(sAh + off) = hi;
            *(uint4*)(sAl + off) = lo;
        }
    }

    const int mW = (wid & 3) * 32;
    const int nW = (wid >> 2) * 64;

    for (int nb = 0; nb < NBLK; nb++) {
        __syncthreads();
        // ---- stage B block (already split bf16 in g_wh/g_wl)
        {
            const int ck = tid & 15;
            const int r0 = (tid >> 4) * 8;
#pragma unroll
            for (int i = 0; i < 8; i++) {
                int r = r0 + i;
                size_t srow = (size_t)(brow + nb * 128 + r) * 128 + ck * 8;
                uint4 bh = *(const uint4*)(g_wh + srow);
                uint4 bl = *(const uint4*)(g_wl + srow);
                int off = r * 256 + ((ck ^ (r & 7)) << 4);
                *(uint4*)(sBh + off) = bh;
                *(uint4*)(sBl + off) = bl;
            }
        }
        __syncthreads();

        float acc[2][8][4];
#pragma unroll
        for (int mt = 0; mt < 2; mt++)
#pragma unroll
            for (int nt = 0; nt < 8; nt++)
#pragma unroll
                for (int q = 0; q < 4; q++) acc[mt][nt][q] = 0.f;

#pragma unroll
        for (int kk = 0; kk < 8; kk++) {
            const int kc = kk * 2;

            uint32_t af[2][2][4];
#pragma unroll
            for (int mt = 0; mt < 2; mt++) {
                int row = mW + mt * 16 + (lane & 15);
                int ch  = kc + (lane >> 4);
                uint32_t off = row * 256 + (((unsigned)(ch ^ (row & 7))) << 4);
                LDSM4(af[0][mt][0], af[0][mt][1], af[0][mt][2], af[0][mt][3], aAh + off);
                LDSM4(af[1][mt][0], af[1][mt][1], af[1][mt][2], af[1][mt][3], aAl + off);
            }

            uint32_t bf[2][8][2];
#pragma unroll
            for (int bt = 0; bt < 4; bt++) {
                int row = nW + bt * 16 + (lane & 7) + ((lane >> 4) << 3);
                int ch  = kc + ((lane >> 3) & 1);
                uint32_t off = row * 256 + (((unsigned)(ch ^ (row & 7))) << 4);
                uint32_t r0, r1, r2, r3;
                LDSM4(r0, r1, r2, r3, aBh + off);
                bf[0][2 * bt][0] = r0; bf[0][2 * bt][1] = r1;
                bf[0][2 * bt + 1][0] = r2; bf[0][2 * bt + 1][1] = r3;
                LDSM4(r0, r1, r2, r3, aBl + off);
                bf[1][2 * bt][0] = r0; bf[1][2 * bt][1] = r1;
                bf[1][2 * bt + 1][0] = r2; bf[1][2 * bt + 1][1] = r3;
            }

#pragma unroll
            for (int mt = 0; mt < 2; mt++)
#pragma unroll
                for (int nt = 0; nt < 8; nt++) {
                    mma16816(acc[mt][nt], af[0][mt], bf[0][nt]);   // hh
                    mma16816(acc[mt][nt], af[0][mt], bf[1][nt]);   // hl
                    mma16816(acc[mt][nt], af[1][mt], bf[0][nt]);   // lh
                }
        }

        // ---- epilogue: bias + store
#pragma unroll
        for (int nt = 0; nt < 8; nt++) {
            int col = nb * 128 + nW + nt * 8 + (lane & 3) * 2;
            float b0 = bih[boff + col]     + bhh[boff + col];
            float b1 = bih[boff + col + 1] + bhh[boff + col + 1];
#pragma unroll
            for (int mt = 0; mt < 2; mt++) {
                size_t row = mBase + mW + mt * 16 + (lane >> 2);
                float2 v01 = make_float2(acc[mt][nt][0] + b0, acc[mt][nt][1] + b1);
                float2 v23 = make_float2(acc[mt][nt][2] + b0, acc[mt][nt][3] + b1);
                *(float2*)&C[row * N + col]       = v01;
                *(float2*)&C[(row + 8) * N + col] = v23;
            }
        }
    }
}

// ---------------- recurrent layer 1 (both dirs), TB=4 ----------------------------
// gx prefetched 2 steps ahead into registers (gxe: now, gxn: t+1, gxf: fetching t+2)
__global__ __launch_bounds__(256, 2)
void rec1_k(const float* __restrict__ whh)
{
    __shared__ alignas(16) float hsf[4 * 64];     // h  [r][j]
    __shared__ float pr[2 * 256 * 5];             // matvec partials [kh][gate*5 + r]

    const int dir = blockIdx.y;
    const int b0  = blockIdx.x * 4;
    const int tid = threadIdx.x;
    const int gp  = tid & 127;
    const int kh  = tid >> 7;

    // weights in registers (j-paired): gates {gp, gp+128}, k in [kh*32, kh*32+32)
    u64 wA[16], wB[16];
    {
        const float* wa = whh + ((size_t)dir * 256 + gp) * 64 + kh * 32;
        const float* wb = wa + (size_t)128 * 64;
#pragma unroll
        for (int q = 0; q < 8; q++) {
            float4 va = *(const float4*)(wa + q * 4);
            float4 vb = *(const float4*)(wb + q * 4);
            wA[2 * q] = pk2(va.x, va.y); wA[2 * q + 1] = pk2(va.z, va.w);
            wB[2 * q] = pk2(vb.x, vb.y); wB[2 * q + 1] = pk2(vb.z, vb.w);
        }
    }
    hsf[tid] = 0.f;

    // epilogue identity: cell (er, ej); gx pipeline depth 2 in registers
    const int er = tid >> 6, ej = tid & 63;
    const float* gbe = g_g1 + (size_t)(b0 + er) * SEQT * 512 + (size_t)dir * 256 + ej;
    float gxe[4], gxn[4];
    {
        const int t0 = dir ? (SEQT - 1) : 0;
        const int t1 = dir ? (SEQT - 2) : 1;
#pragma unroll
        for (int gi = 0; gi < 4; gi++) {
            gxe[gi] = gbe[(size_t)t0 * 512 + 64 * gi];
            gxn[gi] = gbe[(size_t)t1 * 512 + 64 * gi];
        }
    }
    __syncthreads();

    float cc = 0.f;

    for (int tt = 0; tt < SEQT; tt++) {
        const int t   = dir ? (SEQT - 1 - tt) : tt;
        const int tt2 = (tt < SEQT - 2) ? (tt + 2) : (SEQT - 1);
        const int tf  = dir ? (SEQT - 1 - tt2) : tt2;

        // prefetch gx for t+2 (consumed 2 epilogues later -> full latency cover)
        float gxf[4];
#pragma unroll
        for (int gi = 0; gi < 4; gi++)
            gxf[gi] = gbe[(size_t)tf * 512 + 64 * gi];

        // matvec: gates {gp, gp+128}, k-half kh, 4 rows (pure h@W, gx added later)
        u64 aA[4], aB[4];
#pragma unroll
        for (int r = 0; r < 4; r++) { aA[r] = 0ULL; aB[r] = 0ULL; }
        const float* hk = hsf + kh * 32;
#pragma unroll
        for (int q = 0; q < 8; q++) {
            ulonglong2 h0 = *(const ulonglong2*)&hk[0 * 64 + q * 4];
            ulonglong2 h1 = *(const ulonglong2*)&hk[1 * 64 + q * 4];
            ulonglong2 h2 = *(const ulonglong2*)&hk[2 * 64 + q * 4];
            ulonglong2 h3 = *(const ulonglong2*)&hk[3 * 64 + q * 4];
            u64 w0 = wA[2 * q], w1 = wA[2 * q + 1];
            u64 x0 = wB[2 * q], x1 = wB[2 * q + 1];
            aA[0] = fma2(h0.x, w0, aA[0]); aA[0] = fma2(h0.y, w1, aA[0]);
            aB[0] = fma2(h0.x, x0, aB[0]); aB[0] = fma2(h0.y, x1, aB[0]);
            aA[1] = fma2(h1.x, w0, aA[1]); aA[1] = fma2(h1.y, w1, aA[1]);
            aB[1] = fma2(h1.x, x0, aB[1]); aB[1] = fma2(h1.y, x1, aB[1]);
            aA[2] = fma2(h2.x, w0, aA[2]); aA[2] = fma2(h2.y, w1, aA[2]);
            aB[2] = fma2(h2.x, x0, aB[2]); aB[2] = fma2(h2.y, x1, aB[2]);
            aA[3] = fma2(h3.x, w0, aA[3]); aA[3] = fma2(h3.y, w1, aA[3]);
            aB[3] = fma2(h3.x, x0, aB[3]); aB[3] = fma2(h3.y, x1, aB[3]);
        }
        // partial sums -> smem (pad-5, conflict-free)
        float* prk = pr + kh * 1280;
#pragma unroll
        for (int r = 0; r < 4; r++) {
            float2 v = upk2(aA[r]);
            prk[gp * 5 + r] = v.x + v.y;
            v = upk2(aB[r]);
            prk[(gp + 128) * 5 + r] = v.x + v.y;
        }
        __syncthreads();

        // epilogue: cell (er, ej); gx from registers (loaded 2 steps ago)
        {
            float xi = pr[ej * 5 + er]          + pr[1280 + ej * 5 + er]          + gxe[0];
            float xf = pr[(64 + ej) * 5 + er]   + pr[1280 + (64 + ej) * 5 + er]   + gxe[1];
            float xg = pr[(128 + ej) * 5 + er]  + pr[1280 + (128 + ej) * 5 + er]  + gxe[2];
            float xo = pr[(192 + ej) * 5 + er]  + pr[1280 + (192 + ej) * 5 + er]  + gxe[3];
            float iv = sigf(xi), fv = sigf(xf), gv = tnhf(xg), ov = sigf(xo);
            cc = fv * cc + iv * gv;
            float h = ov * tnhf(cc);
            hsf[er * 64 + ej] = h;
            g_h1[((size_t)(b0 + er) * SEQT + t) * 128 + dir * 64 + ej] = h;
        }
#pragma unroll
        for (int gi = 0; gi < 4; gi++) { gxe[gi] = gxn[gi]; gxn[gi] = gxf[gi]; }
        __syncthreads();
    }
}

// ---------------- recurrent layer 2 fwd only, TB=2 -------------------------------
__global__ __launch_bounds__(256, 2)
void rec2_k(const float* __restrict__ whh)
{
    __shared__ alignas(16) float hsf[2 * 64];
    __shared__ float pr[2 * 256 * 3];

    const int b0  = blockIdx.x * 2;
    const int tid = threadIdx.x;
    const int gp  = tid & 127;
    const int kh  = tid >> 7;

    u64 wA[16], wB[16];
    {
        const float* wa = whh + ((size_t)512 + gp) * 64 + kh * 32;   // layer1 dir0
        const float* wb = wa + (size_t)128 * 64;
#pragma unroll
        for (int q = 0; q < 8; q++) {
            float4 va = *(const float4*)(wa + q * 4);
            float4 vb = *(const float4*)(wb + q * 4);
            wA[2 * q] = pk2(va.x, va.y); wA[2 * q + 1] = pk2(va.z, va.w);
            wB[2 * q] = pk2(vb.x, vb.y); wB[2 * q + 1] = pk2(vb.z, vb.w);
        }
    }
    if (tid < 128) hsf[tid] = 0.f;

    const int er = tid >> 6, ej = tid & 63;     // valid for tid<128
    const float* gbe = g_g2 + (size_t)(b0 + er) * SEQT * 256 + ej;
    float gxe[4] = {0.f, 0.f, 0.f, 0.f};
    float gxn[4] = {0.f, 0.f, 0.f, 0.f};
    if (tid < 128) {
#pragma unroll
        for (int gi = 0; gi < 4; gi++) {
            gxe[gi] = gbe[64 * gi];                       // t=0
            gxn[gi] = gbe[(size_t)256 + 64 * gi];         // t=1
        }
    }
    __syncthreads();

    float cc = 0.f;

    for (int tt = 0; tt < SEQT; tt++) {
        const int tf = (tt < SEQT - 2) ? (tt + 2) : (SEQT - 1);

        float gxf[4] = {0.f, 0.f, 0.f, 0.f};
        if (tid < 128) {
#pragma unroll
            for (int gi = 0; gi < 4; gi++)
                gxf[gi] = gbe[(size_t)tf * 256 + 64 * gi];
        }

        u64 aA[2], aB[2];
#pragma unroll
        for (int r = 0; r < 2; r++) { aA[r] = 0ULL; aB[r] = 0ULL; }
        const float* hk = hsf + kh * 32;
#pragma unroll
        for (int q = 0; q < 8; q++) {
            ulonglong2 h0 = *(const ulonglong2*)&hk[0 * 64 + q * 4];
            ulonglong2 h1 = *(const ulonglong2*)&hk[1 * 64 + q * 4];
            u64 w0 = wA[2 * q], w1 = wA[2 * q + 1];
            u64 x0 = wB[2 * q], x1 = wB[2 * q + 1];
            aA[0] = fma2(h0.x, w0, aA[0]); aA[0] = fma2(h0.y, w1, aA[0]);
            aB[0] = fma2(h0.x, x0, aB[0]); aB[0] = fma2(h0.y, x1, aB[0]);
            aA[1] = fma2(h1.x, w0, aA[1]); aA[1] = fma2(h1.y, w1, aA[1]);
            aB[1] = fma2(h1.x, x0, aB[1]); aB[1] = fma2(h1.y, x1, aB[1]);
        }
        float* prk = pr + kh * 768;
#pragma unroll
        for (int r = 0; r < 2; r++) {
            float2 v = upk2(aA[r]);
            prk[gp * 3 + r] = v.x + v.y;
            v = upk2(aB[r]);
            prk[(gp + 128) * 3 + r] = v.x + v.y;
        }
        __syncthreads();

        if (tid < 128) {
            float xi = pr[ej * 3 + er]         + pr[768 + ej * 3 + er]         + gxe[0];
            float xf = pr[(64 + ej) * 3 + er]  + pr[768 + (64 + ej) * 3 + er]  + gxe[1];
            float xg = pr[(128 + ej) * 3 + er] + pr[768 + (128 + ej) * 3 + er] + gxe[2];
            float xo = pr[(192 + ej) * 3 + er] + pr[768 + (192 + ej) * 3 + er] + gxe[3];
            float iv = sigf(xi), fv = sigf(xf), gv = tnhf(xg), ov = sigf(xo);
            cc = fv * cc + iv * gv;
            float h = ov * tnhf(cc);
            hsf[er * 64 + ej] = h;
            if (tt == SEQT - 1) g_h2[(b0 + er) * 64 + ej] = h;
        }
#pragma unroll
        for (int gi = 0; gi < 4; gi++) { gxe[gi] = gxn[gi]; gxn[gi] = gxf[gi]; }
        __syncthreads();
    }
}

// ---------------- final: 1-step layer2-bwd at t=T-1 + FC head -------------------
__global__ void final_k(const float* __restrict__ wih, const float* __restrict__ bih,
                        const float* __restrict__ bhh, const float* __restrict__ fcw,
                        const float* __restrict__ fcb, float* __restrict__ out)
{
    const int b = blockIdx.x;
    const int j = threadIdx.x;   // 64 threads

    __shared__ alignas(16) float xr[128];
    __shared__ float red[64];

    xr[j]      = g_h1[((size_t)b * SEQT + (SEQT - 1)) * 128 + j];
    xr[j + 64] = g_h1[((size_t)b * SEQT + (SEQT - 1)) * 128 + 64 + j];
    __syncthreads();

    const float* wi = wih + 98304 + (size_t)j * 128;
    const float* wg = wih + 98304 + (size_t)(128 + j) * 128;
    const float* wo = wih + 98304 + (size_t)(192 + j) * 128;
    float ai = bih[768 + j]       + bhh[768 + j];
    float ag = bih[768 + 128 + j] + bhh[768 + 128 + j];
    float ao = bih[768 + 192 + j] + bhh[768 + 192 + j];
#pragma unroll 8
    for (int k = 0; k < 128; k += 4) {
        float4 xv = *(const float4*)&xr[k];
        float4 a  = *(const float4*)&wi[k];
        float4 gq = *(const float4*)&wg[k];
        float4 oq = *(const float4*)&wo[k];
        ai += xv.x * a.x  + xv.y * a.y  + xv.z * a.z  + xv.w * a.w;
        ag += xv.x * gq.x + xv.y * gq.y + xv.z * gq.z + xv.w * gq.w;
        ao += xv.x * oq.x + xv.y * oq.y + xv.z * oq.z + xv.w * oq.w;
    }
    float c  = sigf(ai) * tnhf(ag);
    float hb = sigf(ao) * tnhf(c);

    red[j] = fcw[j] * g_h2[b * 64 + j] + fcw[64 + j] * hb;
    __syncthreads();
    if (j < 32) {
        float v = red[j] + red[j + 32];
#pragma unroll
        for (int o = 16; o; o >>= 1) v += __shfl_down_sync(0xffffffffu, v, o);
        if (j == 0) out[b] = v + fcb[0];
    }
}

// ---------------- launch --------------------------------------------------------
extern "C" void kernel_launch(void* const* d_in, const int* in_sizes, int n_in,
                              void* d_out, int out_size)
{
    (void)in_sizes; (void)n_in; (void)out_size;
    const float* x    = (const float*)d_in[0];
    const float* w_ih = (const float*)d_in[1];
    const float* w_hh = (const float*)d_in[2];
    const float* b_ih = (const float*)d_in[3];
    const float* b_hh = (const float*)d_in[4];
    const float* fc_w = (const float*)d_in[5];
    const float* fc_b = (const float*)d_in[6];
    float* out = (float*)d_out;

    const int gemm_smem = 131072;
    cudaFuncSetAttribute(gemm_mma, cudaFuncAttributeMaxDynamicSharedMemorySize, gemm_smem);

    // 0) split-bf16 weight conversion (tiny)
    conv_w_k<<<384, 256>>>(w_ih);
    // 1) layer1 input projection, both dirs (N=512), HMMA split-bf16
    gemm_mma<<<4096, 256, gemm_smem>>>(x, b_ih, b_hh, 0);
    // 2) layer1 recurrence (fwd + bwd), depth-2 gx prefetch
    rec1_k<<<dim3(128, 2), 256>>>(w_hh);
    // 3) layer2-fwd input projection (N=256), HMMA split-bf16
    gemm_mma<<<4096, 256, gemm_smem>>>(x, b_ih, b_hh, 1);
    // 4) layer2-fwd recurrence, keeps only final h
    rec2_k<<<256, 256>>>(w_hh);
    // 5) layer2-bwd single step at t=T-1 + FC head
    final_k<<<dim3(512, 1), 64>>>(w_ih, b_ih, b_hh, fc_w, fc_b, out);
}

// round 16
// speedup vs baseline: 1.0485x; 1.0485x over previous
#include <cuda_runtime.h>
#include <cuda_bf16.h>
#include <cstdint>
#include <cstddef>

typedef unsigned long long u64;

#define BATCH 512
#define SEQT  1024

// ---------------- scratch (static device globals) -------------------------------
__device__ float g_g1[(size_t)BATCH * SEQT * 512];   // layer1 gate preacts (1.07 GB)
__device__ float g_g2[(size_t)BATCH * SEQT * 256];   // layer2-fwd gate preacts (536 MB)
__device__ float g_h1[(size_t)BATCH * SEQT * 128];   // layer1 h [fwd|bwd] fp32 (268 MB)
__device__ float g_h2[BATCH * 64];                   // layer2-fwd final h
__device__ __nv_bfloat16 g_wh[768 * 128];            // w_ih split-bf16 hi: l0d0,l0d1,l1d0
__device__ __nv_bfloat16 g_wl[768 * 128];            // w_ih split-bf16 lo

// ---------------- packed fp32x2 helpers -----------------------------------------
static __device__ __forceinline__ u64 pk2(float a, float b) {
    u64 r;
    asm("mov.b64 %0, {%1, %2};" : "=l"(r) : "r"(__float_as_uint(a)), "r"(__float_as_uint(b)));
    return r;
}
static __device__ __forceinline__ float2 upk2(u64 v) {
    unsigned int lo, hi;
    asm("mov.b64 {%0, %1}, %2;" : "=r"(lo), "=r"(hi) : "l"(v));
    return make_float2(__uint_as_float(lo), __uint_as_float(hi));
}
static __device__ __forceinline__ u64 fma2(u64 a, u64 b, u64 c) {
    u64 d;
    asm("fma.rn.f32x2 %0, %1, %2, %3;" : "=l"(d) : "l"(a), "l"(b), "l"(c));
    return d;
}
// single-MUFU activations via tanh.approx.f32 (sm_75+ baseline PTX)
static __device__ __forceinline__ float tanh_ap(float x) {
    float y;
    asm("tanh.approx.f32 %0, %1;" : "=f"(y) : "f"(x));
    return y;
}
static __device__ __forceinline__ float sigf(float x) {
    return fmaf(tanh_ap(0.5f * x), 0.5f, 0.5f);
}
static __device__ __forceinline__ float tnhf(float x) {
    return tanh_ap(x);
}

// ---------------- mma.sync / ldmatrix helpers ------------------------------------
static __device__ __forceinline__ uint32_t smem_u32(const void* p) {
    uint32_t a;
    asm("{ .reg .u64 t; cvta.to.shared.u64 t, %1; cvt.u32.u64 %0, t; }" : "=r"(a) : "l"(p));
    return a;
}
#define LDSM4(d0, d1, d2, d3, a)                                                     \
    asm volatile("ldmatrix.sync.aligned.m8n8.x4.shared.b16 {%0,%1,%2,%3}, [%4];"     \
                 : "=r"(d0), "=r"(d1), "=r"(d2), "=r"(d3) : "r"(a))

static __device__ __forceinline__ void mma16816(float* d, const uint32_t* a,
                                                const uint32_t* b) {
    asm volatile(
        "mma.sync.aligned.m16n8k16.row.col.f32.bf16.bf16.f32 "
        "{%0,%1,%2,%3}, {%4,%5,%6,%7}, {%8,%9}, {%0,%1,%2,%3};"
        : "+f"(d[0]), "+f"(d[1]), "+f"(d[2]), "+f"(d[3])
        : "r"(a[0]), "r"(a[1]), "r"(a[2]), "r"(a[3]), "r"(b[0]), "r"(b[1]));
}

// split one fp32 into bf16 hi + bf16 lo (residual)
static __device__ __forceinline__ void split8(const float* v, uint4& hi, uint4& lo) {
    unsigned hw[4], lw[4];
#pragma unroll
    for (int p = 0; p < 4; p++) {
        __nv_bfloat16 h0 = __float2bfloat16(v[2 * p]);
        __nv_bfloat16 h1 = __float2bfloat16(v[2 * p + 1]);
        float r0 = v[2 * p]     - __bfloat162float(h0);
        float r1 = v[2 * p + 1] - __bfloat162float(h1);
        __nv_bfloat16 l0 = __float2bfloat16(r0);
        __nv_bfloat16 l1 = __float2bfloat16(r1);
        hw[p] = (unsigned)(*(unsigned short*)&h0) | ((unsigned)(*(unsigned short*)&h1) << 16);
        lw[p] = (unsigned)(*(unsigned short*)&l0) | ((unsigned)(*(unsigned short*)&l1) << 16);
    }
    hi = make_uint4(hw[0], hw[1], hw[2], hw[3]);
    lo = make_uint4(lw[0], lw[1], lw[2], lw[3]);
}

// ---------------- weight split conversion (tiny) --------------------------------
__global__ void conv_w_k(const float* __restrict__ w) {
    int i = blockIdx.x * blockDim.x + threadIdx.x;
    if (i < 768 * 128) {
        float v = w[i];
        __nv_bfloat16 h = __float2bfloat16(v);
        g_wh[i] = h;
        g_wl[i] = __float2bfloat16(v - __bfloat162float(h));
    }
}

// ---------------- HMMA split-bf16 GEMM: C = A[M,128] @ W[N,128]^T + b -----------
__global__ __launch_bounds__(256, 1)
void gemm_mma(const float* __restrict__ x, const float* __restrict__ bih,
              const float* __restrict__ bhh, int which)
{
    const float* Asrc = which ? g_h1 : x;
    float*       C    = which ? g_g2 : g_g1;
    const int N    = which ? 256 : 512;
    const int NBLK = which ? 2 : 4;
    const int boff = which ? 512 : 0;
    const int brow = which ? 512 : 0;      // row offset into g_wh/g_wl

    extern __shared__ __align__(1024) char smem[];
    char* sAh = smem;                      // 32KB each, rows of 256B, chunk16 swizzle
    char* sAl = smem + 32768;
    char* sBh = smem + 65536;
    char* sBl = smem + 98304;
    const uint32_t aAh = smem_u32(sAh), aAl = smem_u32(sAl);
    const uint32_t aBh = smem_u32(sBh), aBl = smem_u32(sBl);

    const int tid  = threadIdx.x;
    const int lane = tid & 31;
    const int wid  = tid >> 5;
    const size_t mBase = (size_t)blockIdx.x * 128;

    // ---- stage A (fp32 -> split bf16), swizzled: off(r,c)=r*256+((c^(r&7))<<4)
    {
        const int ck = tid & 15;
        const int r0 = (tid >> 4) * 8;
#pragma unroll
        for (int i = 0; i < 8; i++) {
            int r = r0 + i;
            float vbuf[8];
            const float4* src = (const float4*)(Asrc + (mBase + r) * 128 + ck * 8);
            float4 v0 = src[0], v1 = src[1];
            vbuf[0] = v0.x; vbuf[1] = v0.y; vbuf[2] = v0.z; vbuf[3] = v0.w;
            vbuf[4] = v1.x; vbuf[5] = v1.y; vbuf[6] = v1.z; vbuf[7] = v1.w;
            uint4 hi, lo;
            split8(vbuf, hi, lo);
            int off = r * 256 + ((ck ^ (r & 7)) << 4);
            *(uint4*)(sAh + off) = hi;
            *(uint4*)(sAl + off) = lo;
        }
    }

    const int mW = (wid & 3) * 32;
    const int nW = (wid >> 2) * 64;

    for (int nb = 0; nb < NBLK; nb++) {
        __syncthreads();
        // ---- stage B block (already split bf16 in g_wh/g_wl)
        {
            const int ck = tid & 15;
            const int r0 = (tid >> 4) * 8;
#pragma unroll
            for (int i = 0; i < 8; i++) {
                int r = r0 + i;
                size_t srow = (size_t)(brow + nb * 128 + r) * 128 + ck * 8;
                uint4 bh = *(const uint4*)(g_wh + srow);
                uint4 bl = *(const uint4*)(g_wl + srow);
                int off = r * 256 + ((ck ^ (r & 7)) << 4);
                *(uint4*)(sBh + off) = bh;
                *(uint4*)(sBl + off) = bl;
            }
        }
        __syncthreads();

        float acc[2][8][4];
#pragma unroll
        for (int mt = 0; mt < 2; mt++)
#pragma unroll
            for (int nt = 0; nt < 8; nt++)
#pragma unroll
                for (int q = 0; q < 4; q++) acc[mt][nt][q] = 0.f;

#pragma unroll
        for (int kk = 0; kk < 8; kk++) {
            const int kc = kk * 2;

            uint32_t af[2][2][4];
#pragma unroll
            for (int mt = 0; mt < 2; mt++) {
                int row = mW + mt * 16 + (lane & 15);
                int ch  = kc + (lane >> 4);
                uint32_t off = row * 256 + (((unsigned)(ch ^ (row & 7))) << 4);
                LDSM4(af[0][mt][0], af[0][mt][1], af[0][mt][2], af[0][mt][3], aAh + off);
                LDSM4(af[1][mt][0], af[1][mt][1], af[1][mt][2], af[1][mt][3], aAl + off);
            }

            uint32_t bf[2][8][2];
#pragma unroll
            for (int bt = 0; bt < 4; bt++) {
                int row = nW + bt * 16 + (lane & 7) + ((lane >> 4) << 3);
                int ch  = kc + ((lane >> 3) & 1);
                uint32_t off = row * 256 + (((unsigned)(ch ^ (row & 7))) << 4);
                uint32_t r0, r1, r2, r3;
                LDSM4(r0, r1, r2, r3, aBh + off);
                bf[0][2 * bt][0] = r0; bf[0][2 * bt][1] = r1;
                bf[0][2 * bt + 1][0] = r2; bf[0][2 * bt + 1][1] = r3;
                LDSM4(r0, r1, r2, r3, aBl + off);
                bf[1][2 * bt][0] = r0; bf[1][2 * bt][1] = r1;
                bf[1][2 * bt + 1][0] = r2; bf[1][2 * bt + 1][1] = r3;
            }

#pragma unroll
            for (int mt = 0; mt < 2; mt++)
#pragma unroll
                for (int nt = 0; nt < 8; nt++) {
                    mma16816(acc[mt][nt], af[0][mt], bf[0][nt]);   // hh
                    mma16816(acc[mt][nt], af[0][mt], bf[1][nt]);   // hl
                    mma16816(acc[mt][nt], af[1][mt], bf[0][nt]);   // lh
                }
        }

        // ---- epilogue: bias + store
#pragma unroll
        for (int nt = 0; nt < 8; nt++) {
            int col = nb * 128 + nW + nt * 8 + (lane & 3) * 2;
            float b0 = bih[boff + col]     + bhh[boff + col];
            float b1 = bih[boff + col + 1] + bhh[boff + col + 1];
#pragma unroll
            for (int mt = 0; mt < 2; mt++) {
                size_t row = mBase + mW + mt * 16 + (lane >> 2);
                float2 v01 = make_float2(acc[mt][nt][0] + b0, acc[mt][nt][1] + b1);
                float2 v23 = make_float2(acc[mt][nt][2] + b0, acc[mt][nt][3] + b1);
                *(float2*)&C[row * N + col]       = v01;
                *(float2*)&C[(row + 8) * N + col] = v23;
            }
        }
    }
}

// ---------------- recurrent layer 1 (both dirs), TB=4 ----------------------------
// R12 structure: register gx prefetch depth 1; tanh.approx activations.
__global__ __launch_bounds__(256, 2)
void rec1_k(const float* __restrict__ whh)
{
    __shared__ alignas(16) float hsf[4 * 64];     // h  [r][j]
    __shared__ float pr[2 * 256 * 5];             // matvec partials [kh][gate*5 + r]

    const int dir = blockIdx.y;
    const int b0  = blockIdx.x * 4;
    const int tid = threadIdx.x;
    const int gp  = tid & 127;
    const int kh  = tid >> 7;

    // weights in registers (j-paired): gates {gp, gp+128}, k in [kh*32, kh*32+32)
    u64 wA[16], wB[16];
    {
        const float* wa = whh + ((size_t)dir * 256 + gp) * 64 + kh * 32;
        const float* wb = wa + (size_t)128 * 64;
#pragma unroll
        for (int q = 0; q < 8; q++) {
            float4 va = *(const float4*)(wa + q * 4);
            float4 vb = *(const float4*)(wb + q * 4);
            wA[2 * q] = pk2(va.x, va.y); wA[2 * q + 1] = pk2(va.z, va.w);
            wB[2 * q] = pk2(vb.x, vb.y); wB[2 * q + 1] = pk2(vb.z, vb.w);
        }
    }
    hsf[tid] = 0.f;

    // epilogue identity: cell (er, ej); its 4 gate-gx values live in registers
    const int er = tid >> 6, ej = tid & 63;
    const float* gbe = g_g1 + (size_t)(b0 + er) * SEQT * 512 + (size_t)dir * 256 + ej;
    float gxe[4];
    {
        const int t0 = dir ? (SEQT - 1) : 0;
#pragma unroll
        for (int gi = 0; gi < 4; gi++)
            gxe[gi] = gbe[(size_t)t0 * 512 + 64 * gi];
    }
    __syncthreads();

    float cc = 0.f;

    for (int tt = 0; tt < SEQT; tt++) {
        const int t   = dir ? (SEQT - 1 - tt) : tt;
        const int ttn = (tt < SEQT - 1) ? (tt + 1) : tt;
        const int tn  = dir ? (SEQT - 1 - ttn) : ttn;

        // prefetch next step's gx for THIS thread's cell (consumed next epilogue)
        float gxf[4];
#pragma unroll
        for (int gi = 0; gi < 4; gi++)
            gxf[gi] = gbe[(size_t)tn * 512 + 64 * gi];

        // matvec: gates {gp, gp+128}, k-half kh, 4 rows (pure h@W, gx added later)
        u64 aA[4], aB[4];
#pragma unroll
        for (int r = 0; r < 4; r++) { aA[r] = 0ULL; aB[r] = 0ULL; }
        const float* hk = hsf + kh * 32;
#pragma unroll
        for (int q = 0; q < 8; q++) {
            ulonglong2 h0 = *(const ulonglong2*)&hk[0 * 64 + q * 4];
            ulonglong2 h1 = *(const ulonglong2*)&hk[1 * 64 + q * 4];
            ulonglong2 h2 = *(const ulonglong2*)&hk[2 * 64 + q * 4];
            ulonglong2 h3 = *(const ulonglong2*)&hk[3 * 64 + q * 4];
            u64 w0 = wA[2 * q], w1 = wA[2 * q + 1];
            u64 x0 = wB[2 * q], x1 = wB[2 * q + 1];
            aA[0] = fma2(h0.x, w0, aA[0]); aA[0] = fma2(h0.y, w1, aA[0]);
            aB[0] = fma2(h0.x, x0, aB[0]); aB[0] = fma2(h0.y, x1, aB[0]);
            aA[1] = fma2(h1.x, w0, aA[1]); aA[1] = fma2(h1.y, w1, aA[1]);
            aB[1] = fma2(h1.x, x0, aB[1]); aB[1] = fma2(h1.y, x1, aB[1]);
            aA[2] = fma2(h2.x, w0, aA[2]); aA[2] = fma2(h2.y, w1, aA[2]);
            aB[2] = fma2(h2.x, x0, aB[2]); aB[2] = fma2(h2.y, x1, aB[2]);
            aA[3] = fma2(h3.x, w0, aA[3]); aA[3] = fma2(h3.y, w1, aA[3]);
            aB[3] = fma2(h3.x, x0, aB[3]); aB[3] = fma2(h3.y, x1, aB[3]);
        }
        // partial sums -> smem (pad-5, conflict-free)
        float* prk = pr + kh * 1280;
#pragma unroll
        for (int r = 0; r < 4; r++) {
            float2 v = upk2(aA[r]);
            prk[gp * 5 + r] = v.x + v.y;
            v = upk2(aB[r]);
            prk[(gp + 128) * 5 + r] = v.x + v.y;
        }
        __syncthreads();

        // epilogue: cell (er, ej); gx from registers
        {
            float xi = pr[ej * 5 + er]          + pr[1280 + ej * 5 + er]          + gxe[0];
            float xf = pr[(64 + ej) * 5 + er]   + pr[1280 + (64 + ej) * 5 + er]   + gxe[1];
            float xg = pr[(128 + ej) * 5 + er]  + pr[1280 + (128 + ej) * 5 + er]  + gxe[2];
            float xo = pr[(192 + ej) * 5 + er]  + pr[1280 + (192 + ej) * 5 + er]  + gxe[3];
            float iv = sigf(xi), fv = sigf(xf), gv = tnhf(xg), ov = sigf(xo);
            cc = fv * cc + iv * gv;
            float h = ov * tnhf(cc);
            hsf[er * 64 + ej] = h;
            g_h1[((size_t)(b0 + er) * SEQT + t) * 128 + dir * 64 + ej] = h;
        }
#pragma unroll
        for (int gi = 0; gi < 4; gi++) gxe[gi] = gxf[gi];
        __syncthreads();
    }
}

// ---------------- recurrent layer 2 fwd only, TB=2 -------------------------------
__global__ __launch_bounds__(256, 2)
void rec2_k(const float* __restrict__ whh)
{
    __shared__ alignas(16) float hsf[2 * 64];
    __shared__ float pr[2 * 256 * 3];

    const int b0  = blockIdx.x * 2;
    const int tid = threadIdx.x;
    const int gp  = tid & 127;
    const int kh  = tid >> 7;

    u64 wA[16], wB[16];
    {
        const float* wa = whh + ((size_t)512 + gp) * 64 + kh * 32;   // layer1 dir0
        const float* wb = wa + (size_t)128 * 64;
#pragma unroll
        for (int q = 0; q < 8; q++) {
            float4 va = *(const float4*)(wa + q * 4);
            float4 vb = *(const float4*)(wb + q * 4);
            wA[2 * q] = pk2(va.x, va.y); wA[2 * q + 1] = pk2(va.z, va.w);
            wB[2 * q] = pk2(vb.x, vb.y); wB[2 * q + 1] = pk2(vb.z, vb.w);
        }
    }
    if (tid < 128) hsf[tid] = 0.f;

    const int er = tid >> 6, ej = tid & 63;     // valid for tid<128
    const float* gbe = g_g2 + (size_t)(b0 + er) * SEQT * 256 + ej;
    float gxe[4] = {0.f, 0.f, 0.f, 0.f};
    if (tid < 128) {
#pragma unroll
        for (int gi = 0; gi < 4; gi++)
            gxe[gi] = gbe[64 * gi];             // t=0
    }
    __syncthreads();

    float cc = 0.f;

    for (int tt = 0; tt < SEQT; tt++) {
        const int tn = (tt < SEQT - 1) ? (tt + 1) : tt;

        float gxf[4] = {0.f, 0.f, 0.f, 0.f};
        if (tid < 128) {
#pragma unroll
            for (int gi = 0; gi < 4; gi++)
                gxf[gi] = gbe[(size_t)tn * 256 + 64 * gi];
        }

        u64 aA[2], aB[2];
#pragma unroll
        for (int r = 0; r < 2; r++) { aA[r] = 0ULL; aB[r] = 0ULL; }
        const float* hk = hsf + kh * 32;
#pragma unroll
        for (int q = 0; q < 8; q++) {
            ulonglong2 h0 = *(const ulonglong2*)&hk[0 * 64 + q * 4];
            ulonglong2 h1 = *(const ulonglong2*)&hk[1 * 64 + q * 4];
            u64 w0 = wA[2 * q], w1 = wA[2 * q + 1];
            u64 x0 = wB[2 * q], x1 = wB[2 * q + 1];
            aA[0] = fma2(h0.x, w0, aA[0]); aA[0] = fma2(h0.y, w1, aA[0]);
            aB[0] = fma2(h0.x, x0, aB[0]); aB[0] = fma2(h0.y, x1, aB[0]);
            aA[1] = fma2(h1.x, w0, aA[1]); aA[1] = fma2(h1.y, w1, aA[1]);
            aB[1] = fma2(h1.x, x0, aB[1]); aB[1] = fma2(h1.y, x1, aB[1]);
        }
        float* prk = pr + kh * 768;
#pragma unroll
        for (int r = 0; r < 2; r++) {
            float2 v = upk2(aA[r]);
            prk[gp * 3 + r] = v.x + v.y;
            v = upk2(aB[r]);
            prk[(gp + 128) * 3 + r] = v.x + v.y;
        }
        __syncthreads();

        if (tid < 128) {
            float xi = pr[ej * 3 + er]         + pr[768 + ej * 3 + er]         + gxe[0];
            float xf = pr[(64 + ej) * 3 + er]  + pr[768 + (64 + ej) * 3 + er]  + gxe[1];
            float xg = pr[(128 + ej) * 3 + er] + pr[768 + (128 + ej) * 3 + er] + gxe[2];
            float xo = pr[(192 + ej) * 3 + er] + pr[768 + (192 + ej) * 3 + er] + gxe[3];
            float iv = sigf(xi), fv = sigf(xf), gv = tnhf(xg), ov = sigf(xo);
            cc = fv * cc + iv * gv;
            float h = ov * tnhf(cc);
            hsf[er * 64 + ej] = h;
            if (tt == SEQT - 1) g_h2[(b0 + er) * 64 + ej] = h;
        }
#pragma unroll
        for (int gi = 0; gi < 4; gi++) gxe[gi] = gxf[gi];
        __syncthreads();
    }
}

// ---------------- final: 1-step layer2-bwd at t=T-1 + FC head -------------------
__global__ void final_k(const float* __restrict__ wih, const float* __restrict__ bih,
                        const float* __restrict__ bhh, const float* __restrict__ fcw,
                        const float* __restrict__ fcb, float* __restrict__ out)
{
    const int b = blockIdx.x;
    const int j = threadIdx.x;   // 64 threads

    __shared__ alignas(16) float xr[128];
    __shared__ float red[64];

    xr[j]      = g_h1[((size_t)b * SEQT + (SEQT - 1)) * 128 + j];
    xr[j + 64] = g_h1[((size_t)b * SEQT + (SEQT - 1)) * 128 + 64 + j];
    __syncthreads();

    const float* wi = wih + 98304 + (size_t)j * 128;
    const float* wg = wih + 98304 + (size_t)(128 + j) * 128;
    const float* wo = wih + 98304 + (size_t)(192 + j) * 128;
    float ai = bih[768 + j]       + bhh[768 + j];
    float ag = bih[768 + 128 + j] + bhh[768 + 128 + j];
    float ao = bih[768 + 192 + j] + bhh[768 + 192 + j];
#pragma unroll 8
    for (int k = 0; k < 128; k += 4) {
        float4 xv = *(const float4*)&xr[k];
        float4 a  = *(const float4*)&wi[k];
        float4 gq = *(const float4*)&wg[k];
        float4 oq = *(const float4*)&wo[k];
        ai += xv.x * a.x  + xv.y * a.y  + xv.z * a.z  + xv.w * a.w;
        ag += xv.x * gq.x + xv.y * gq.y + xv.z * gq.z + xv.w * gq.w;
        ao += xv.x * oq.x + xv.y * oq.y + xv.z * oq.z + xv.w * oq.w;
    }
    float c  = sigf(ai) * tnhf(ag);
    float hb = sigf(ao) * tnhf(c);

    red[j] = fcw[j] * g_h2[b * 64 + j] + fcw[64 + j] * hb;
    __syncthreads();
    if (j < 32) {
        float v = red[j] + red[j + 32];
#pragma unroll
        for (int o = 16; o; o >>= 1) v += __shfl_down_sync(0xffffffffu, v, o);
        if (j == 0) out[b] = v + fcb[0];
    }
}

// ---------------- launch --------------------------------------------------------
extern "C" void kernel_launch(void* const* d_in, const int* in_sizes, int n_in,
                              void* d_out, int out_size)
{
    (void)in_sizes; (void)n_in; (void)out_size;
    const float* x    = (const float*)d_in[0];
    const float* w_ih = (const float*)d_in[1];
    const float* w_hh = (const float*)d_in[2];
    const float* b_ih = (const float*)d_in[3];
    const float* b_hh = (const float*)d_in[4];
    const float* fc_w = (const float*)d_in[5];
    const float* fc_b = (const float*)d_in[6];
    float* out = (float*)d_out;

    const int gemm_smem = 131072;
    cudaFuncSetAttribute(gemm_mma, cudaFuncAttributeMaxDynamicSharedMemorySize, gemm_smem);

    // 0) split-bf16 weight conversion (tiny)
    conv_w_k<<<384, 256>>>(w_ih);
    // 1) layer1 input projection, both dirs (N=512), HMMA split-bf16
    gemm_mma<<<4096, 256, gemm_smem>>>(x, b_ih, b_hh, 0);
    // 2) layer1 recurrence (fwd + bwd), register gx prefetch, tanh.approx
    rec1_k<<<dim3(128, 2), 256>>>(w_hh);
    // 3) layer2-fwd input projection (N=256), HMMA split-bf16
    gemm_mma<<<4096, 256, gemm_smem>>>(x, b_ih, b_hh, 1);
    // 4) layer2-fwd recurrence, keeps only final h
    rec2_k<<<256, 256>>>(w_hh);
    // 5) layer2-bwd single step at t=T-1 + FC head
    final_k<<<dim3(512, 1), 64>>>(w_ih, b_ih, b_hh, fc_w, fc_b, out);
}